// round 5
// baseline (speedup 1.0000x reference)
#include <cuda_runtime.h>
#include <math.h>

#define BDIM 2048
#define ODIM 256
#define IDIM 256

typedef unsigned long long u64;

// Scratch. g_u[j][b] = -K*cos(phi0+x[b,j]); g_v[j][b] = K*sin(phi0+x[b,j])
// g_p[j][i] = cos(off[i,j]); g_q[j][i] = sin(off[i,j])
__device__ float g_u[IDIM * BDIM];
__device__ float g_v[IDIM * BDIM];
__device__ float g_p[IDIM * ODIM];
__device__ float g_q[IDIM * ODIM];

// ---------- packed f32x2 helpers ----------
__device__ __forceinline__ u64 fma2(u64 a, u64 b, u64 c) {
    u64 d;
    asm("fma.rn.f32x2 %0, %1, %2, %3;" : "=l"(d) : "l"(a), "l"(b), "l"(c));
    return d;
}
__device__ __forceinline__ u64 add2(u64 a, u64 b) {
    u64 d;
    asm("add.rn.f32x2 %0, %1, %2;" : "=l"(d) : "l"(a), "l"(b));
    return d;
}
__device__ __forceinline__ u64 mul2(u64 a, u64 b) {
    u64 d;
    asm("mul.rn.f32x2 %0, %1, %2;" : "=l"(d) : "l"(a), "l"(b));
    return d;
}
__device__ __forceinline__ float frcp(float x) {
    float r;
    asm("rcp.approx.ftz.f32 %0, %1;" : "=f"(r) : "f"(x));
    return r;
}
__device__ __forceinline__ u64 rcp2(u64 x) {
    float lo, hi;
    asm("mov.b64 {%0, %1}, %2;" : "=f"(lo), "=f"(hi) : "l"(x));
    lo = frcp(lo);
    hi = frcp(hi);
    u64 r;
    asm("mov.b64 %0, {%1, %2};" : "=l"(r) : "f"(lo), "f"(hi));
    return r;
}
__device__ __forceinline__ u64 pack2(float lo, float hi) {
    u64 r;
    asm("mov.b64 %0, {%1, %2};" : "=l"(r) : "f"(lo), "f"(hi));
    return r;
}
__device__ __forceinline__ void unpack2(u64 v, float& lo, float& hi) {
    asm("mov.b64 {%0, %1}, %2;" : "=f"(lo), "=f"(hi) : "l"(v));
}

// ---------- fused prep: uv transpose (512) + pq transpose (64) + out-init (512)
__global__ void prep_all(const float* __restrict__ x,
                         const float* __restrict__ off,
                         float* __restrict__ out, float K, float phi0) {
    const int bx = blockIdx.x;
    if (bx < 512) {
        __shared__ float tc[32][33];
        __shared__ float ts[32][33];
        const int b0 = (bx >> 3) * 32;
        const int j0 = (bx & 7) * 32;
#pragma unroll
        for (int k = 0; k < 4; k++) {
            int lin = threadIdx.x + k * 256;
            int bl = lin >> 5, jl = lin & 31;
            float s, c;
            __sincosf(phi0 + x[(b0 + bl) * IDIM + j0 + jl], &s, &c);
            tc[jl][bl] = c;
            ts[jl][bl] = s;
        }
        __syncthreads();
#pragma unroll
        for (int k = 0; k < 4; k++) {
            int lin = threadIdx.x + k * 256;
            int jl = lin >> 5, bl = lin & 31;
            g_u[(j0 + jl) * BDIM + b0 + bl] = -K * tc[jl][bl];
            g_v[(j0 + jl) * BDIM + b0 + bl] = K * ts[jl][bl];
        }
    } else if (bx < 576) {
        __shared__ float tc[32][33];
        __shared__ float ts[32][33];
        const int r = bx - 512;
        const int i0 = (r >> 3) * 32;
        const int j0 = (r & 7) * 32;
#pragma unroll
        for (int k = 0; k < 4; k++) {
            int lin = threadIdx.x + k * 256;
            int il = lin >> 5, jl = lin & 31;
            float s, c;
            __sincosf(off[(i0 + il) * IDIM + j0 + jl], &s, &c);
            tc[jl][il] = c;
            ts[jl][il] = s;
        }
        __syncthreads();
#pragma unroll
        for (int k = 0; k < 4; k++) {
            int lin = threadIdx.x + k * 256;
            int jl = lin >> 5, il = lin & 31;
            g_p[(j0 + jl) * ODIM + i0 + il] = tc[jl][il];
            g_q[(j0 + jl) * ODIM + i0 + il] = ts[jl][il];
        }
    } else {
        // init out = IDIM (base of T-sum); 512 blocks x 256 thr x float4
        int idx = (bx - 576) * 256 + threadIdx.x;
        float4 v = {(float)IDIM, (float)IDIM, (float)IDIM, (float)IDIM};
        ((float4*)out)[idx] = v;
    }
}

// quad-j combine: acc += (s01*m23 + s23*m01) * rcp(m01*m23)
#define QCOMB(ACC, U, V, PP, QP)                                        \
    do {                                                                \
        u64 d0 = fma2(U[0], PP[0], fma2(V[0], QP[0], C22));             \
        u64 d1 = fma2(U[1], PP[1], fma2(V[1], QP[1], C22));             \
        u64 d2 = fma2(U[2], PP[2], fma2(V[2], QP[2], C22));             \
        u64 d3 = fma2(U[3], PP[3], fma2(V[3], QP[3], C22));             \
        u64 s01 = add2(d0, d1), m01 = mul2(d0, d1);                     \
        u64 s23 = add2(d2, d3), m23 = mul2(d2, d3);                     \
        u64 num = fma2(s23, m01, mul2(s01, m23));                       \
        u64 den = mul2(m01, m23);                                       \
        ACC = fma2(num, rcp2(den), ACC);                                \
    } while (0)

// ---------- main: persistent CTAs, BM=128 x BN=64 tiles, BK=16 chunks ------
// 1024 work items = 64 spatial tiles x 16 j-chunks (spatial-major).
// Per thread: 8 b (4 packed slots) x 4 i. out += D * partial via atomics.
__global__ __launch_bounds__(256, 1) void photonic_main(float* __restrict__ out,
                                                        float C2, float D) {
    __shared__ float su[2][16][128];
    __shared__ float sv[2][16][128];
    __shared__ float sp[2][16][64];
    __shared__ float sq[2][16][64];

    const int tid = threadIdx.x;
    const int bg = tid & 15;        // b-group (8 b each)
    const int ig = tid >> 4;        // i-group (4 i each)
    const int half = ig & 1;        // stagger for conflict-free LDS.128
    const int ubase = bg * 8 + half * 4;

    const int lruv = tid >> 5, lcuv = (tid & 31) * 4;   // u/v loader
    const int lrpq = tid >> 4, lcpq = (tid & 15) * 4;   // p/q loader

    const int NW = 1024;
    const int G = gridDim.x;
    const int wbeg = (int)(((long long)blockIdx.x * NW) / G);
    const int wend = (int)(((long long)(blockIdx.x + 1) * NW) / G);
    if (wbeg >= wend) return;

    const u64 C22 = pack2(C2, C2);
    u64 acc[4][4];

    float4 ru0, ru1, rv0, rv1, rp4, rq4;
    auto gload = [&](int w) {
        int spat = w >> 4, kc = w & 15;
        int b0 = (spat >> 2) * 128;
        int i0 = (spat & 3) * 64;
        int j0 = kc * 16;
        const float* pu = g_u + (size_t)(j0 + lruv) * BDIM + b0 + lcuv;
        const float* pv = g_v + (size_t)(j0 + lruv) * BDIM + b0 + lcuv;
        ru0 = *(const float4*)pu;
        ru1 = *(const float4*)(pu + 8 * BDIM);
        rv0 = *(const float4*)pv;
        rv1 = *(const float4*)(pv + 8 * BDIM);
        rp4 = *(const float4*)(g_p + (size_t)(j0 + lrpq) * ODIM + i0 + lcpq);
        rq4 = *(const float4*)(g_q + (size_t)(j0 + lrpq) * ODIM + i0 + lcpq);
    };
    auto sstore = [&](int bf) {
        *(float4*)&su[bf][lruv][lcuv] = ru0;
        *(float4*)&su[bf][lruv + 8][lcuv] = ru1;
        *(float4*)&sv[bf][lruv][lcuv] = rv0;
        *(float4*)&sv[bf][lruv + 8][lcuv] = rv1;
        *(float4*)&sp[bf][lrpq][lcpq] = rp4;
        *(float4*)&sq[bf][lrpq][lcpq] = rq4;
    };
    auto zacc = [&]() {
#pragma unroll
        for (int s = 0; s < 4; s++)
#pragma unroll
            for (int i = 0; i < 4; i++) acc[s][i] = 0ull;
    };
    auto flush = [&](int spat) {
        int b0 = (spat >> 2) * 128;
        int i0 = (spat & 3) * 64;
        int rows[4] = {ubase, ubase + 2, ubase ^ 4, (ubase ^ 4) + 2};
#pragma unroll
        for (int s = 0; s < 4; s++) {
#pragma unroll
            for (int i = 0; i < 4; i++) {
                float lo, hi;
                unpack2(acc[s][i], lo, hi);
                int col = i0 + ig * 4 + i;
                atomicAdd(&out[(size_t)(b0 + rows[s]) * ODIM + col], D * lo);
                atomicAdd(&out[(size_t)(b0 + rows[s] + 1) * ODIM + col], D * hi);
            }
        }
    };

    int cur = -1, bf = 0;
    gload(wbeg);
    for (int w = wbeg; w < wend; w++) {
        int spat = w >> 4;
        if (spat != cur) {
            if (cur >= 0) flush(cur);
            zacc();
            cur = spat;
        }
        sstore(bf);
        __syncthreads();
        if (w + 1 < wend) gload(w + 1);

#pragma unroll
        for (int jj = 0; jj < 16; jj += 4) {
            u64 Uax[4], Uay[4], Ubx[4], Uby[4];
            u64 Vax[4], Vay[4], Vbx[4], Vby[4];
            float Pr[4][4], Qr[4][4];
#pragma unroll
            for (int k = 0; k < 4; k++) {
                ulonglong2 t;
                t = *(const ulonglong2*)&su[bf][jj + k][ubase];
                Uax[k] = t.x; Uay[k] = t.y;
                t = *(const ulonglong2*)&su[bf][jj + k][ubase ^ 4];
                Ubx[k] = t.x; Uby[k] = t.y;
                t = *(const ulonglong2*)&sv[bf][jj + k][ubase];
                Vax[k] = t.x; Vay[k] = t.y;
                t = *(const ulonglong2*)&sv[bf][jj + k][ubase ^ 4];
                Vbx[k] = t.x; Vby[k] = t.y;
                float4 p = *(const float4*)&sp[bf][jj + k][ig * 4];
                Pr[k][0] = p.x; Pr[k][1] = p.y; Pr[k][2] = p.z; Pr[k][3] = p.w;
                float4 q = *(const float4*)&sq[bf][jj + k][ig * 4];
                Qr[k][0] = q.x; Qr[k][1] = q.y; Qr[k][2] = q.z; Qr[k][3] = q.w;
            }
#pragma unroll
            for (int i = 0; i < 4; i++) {
                u64 Pp[4], Qp[4];
#pragma unroll
                for (int k = 0; k < 4; k++) {
                    Pp[k] = pack2(Pr[k][i], Pr[k][i]);
                    Qp[k] = pack2(Qr[k][i], Qr[k][i]);
                }
                QCOMB(acc[0][i], Uax, Vax, Pp, Qp);
                QCOMB(acc[1][i], Uay, Vay, Pp, Qp);
                QCOMB(acc[2][i], Ubx, Vbx, Pp, Qp);
                QCOMB(acc[3][i], Uby, Vby, Pp, Qp);
            }
        }

        __syncthreads();
        bf ^= 1;
    }
    flush(cur);
}

extern "C" void kernel_launch(void* const* d_in, const int* in_sizes, int n_in,
                              void* d_out, int out_size) {
    const float* x   = (const float*)d_in[0];  // input_matrix [2048, 256]
    const float* off = (const float*)d_in[1];  // phase_offset [256, 256]
    float* out = (float*)d_out;                // [2048, 256]

    const double PI = 3.14159265358979323846;
    const double RADIUS = 5e-6, KAPPA = 0.1, N_EFF = 3.48, LAMBDA = 1.55e-6,
                 LOSS_A = 0.99;
    double t = sqrt(1.0 - KAPPA);
    double at = LOSS_A * t;
    float K  = (float)(2.0 * at);
    float C2 = (float)(1.0 + at * at);
    float D  = (float)(-(1.0 - t * t) * (1.0 - LOSS_A * LOSS_A));
    float phi0 = (float)fmod(2.0 * PI * N_EFF * (2.0 * PI * RADIUS) / LAMBDA,
                             2.0 * PI);

    prep_all<<<1088, 256>>>(x, off, out, K, phi0);
    photonic_main<<<296, 256>>>(out, C2, D);
}

// round 7
// speedup vs baseline: 2.1622x; 2.1622x over previous
#include <cuda_runtime.h>
#include <math.h>

#define BDIM 2048
#define ODIM 256
#define IDIM 256

typedef unsigned long long u64;
typedef unsigned int u32;

// Scratch. g_u[j][b] = -K*cos(phi0+x[b,j]); g_v[j][b] = K*sin(phi0+x[b,j])
// g_pd[j][2i..2i+1] = dup cos(off[i,j]); g_qd = dup sin(off[i,j])
__device__ float g_u[IDIM * BDIM];
__device__ float g_v[IDIM * BDIM];
__device__ float g_pd[IDIM * 2 * ODIM];
__device__ float g_qd[IDIM * 2 * ODIM];

// ---------- packed f32x2 helpers ----------
__device__ __forceinline__ u64 fma2(u64 a, u64 b, u64 c) {
    u64 d;
    asm("fma.rn.f32x2 %0, %1, %2, %3;" : "=l"(d) : "l"(a), "l"(b), "l"(c));
    return d;
}
__device__ __forceinline__ u64 add2(u64 a, u64 b) {
    u64 d;
    asm("add.rn.f32x2 %0, %1, %2;" : "=l"(d) : "l"(a), "l"(b));
    return d;
}
__device__ __forceinline__ u64 mul2(u64 a, u64 b) {
    u64 d;
    asm("mul.rn.f32x2 %0, %1, %2;" : "=l"(d) : "l"(a), "l"(b));
    return d;
}
__device__ __forceinline__ float frcp(float x) {
    float r;
    asm("rcp.approx.ftz.f32 %0, %1;" : "=f"(r) : "f"(x));
    return r;
}
__device__ __forceinline__ u64 rcp2(u64 x) {
    float lo, hi;
    asm("mov.b64 {%0, %1}, %2;" : "=f"(lo), "=f"(hi) : "l"(x));
    lo = frcp(lo);
    hi = frcp(hi);
    u64 r;
    asm("mov.b64 %0, {%1, %2};" : "=l"(r) : "f"(lo), "f"(hi));
    return r;
}
__device__ __forceinline__ u64 pack2(float lo, float hi) {
    u64 r;
    asm("mov.b64 %0, {%1, %2};" : "=l"(r) : "f"(lo), "f"(hi));
    return r;
}
__device__ __forceinline__ void unpack2(u64 v, float& lo, float& hi) {
    asm("mov.b64 {%0, %1}, %2;" : "=f"(lo), "=f"(hi) : "l"(v));
}

// ---------- cp.async (LDGSTS) ----------
__device__ __forceinline__ void cpasync16(u32 saddr, const void* gptr) {
    asm volatile("cp.async.cg.shared.global [%0], [%1], 16;" ::"r"(saddr),
                 "l"(gptr));
}
#define CP_COMMIT() asm volatile("cp.async.commit_group;" ::: "memory")
#define CP_WAIT(N) asm volatile("cp.async.wait_group %0;" ::"n"(N) : "memory")

// ---------- fused prep: uv transpose (512 blocks) + pq dup transpose (64) ---
__global__ void prep_all(const float* __restrict__ x,
                         const float* __restrict__ off, float K, float phi0) {
    __shared__ float tc[32][33];
    __shared__ float ts[32][33];
    const int bx = blockIdx.x;
    if (bx < 512) {
        const int b0 = (bx >> 3) * 32;
        const int j0 = (bx & 7) * 32;
#pragma unroll
        for (int k = 0; k < 4; k++) {
            int lin = threadIdx.x + k * 256;
            int bl = lin >> 5, jl = lin & 31;
            float s, c;
            __sincosf(phi0 + x[(b0 + bl) * IDIM + j0 + jl], &s, &c);
            tc[jl][bl] = c;
            ts[jl][bl] = s;
        }
        __syncthreads();
#pragma unroll
        for (int k = 0; k < 4; k++) {
            int lin = threadIdx.x + k * 256;
            int jl = lin >> 5, bl = lin & 31;
            g_u[(j0 + jl) * BDIM + b0 + bl] = -K * tc[jl][bl];
            g_v[(j0 + jl) * BDIM + b0 + bl] = K * ts[jl][bl];
        }
    } else {
        const int r = bx - 512;
        const int i0 = (r >> 3) * 32;
        const int j0 = (r & 7) * 32;
#pragma unroll
        for (int k = 0; k < 4; k++) {
            int lin = threadIdx.x + k * 256;
            int il = lin >> 5, jl = lin & 31;
            float s, c;
            __sincosf(off[(i0 + il) * IDIM + j0 + jl], &s, &c);
            tc[jl][il] = c;
            ts[jl][il] = s;
        }
        __syncthreads();
#pragma unroll
        for (int k = 0; k < 4; k++) {
            int lin = threadIdx.x + k * 256;
            int jl = lin >> 5, il = lin & 31;
            float c = tc[jl][il], s = ts[jl][il];
            float2 cc = {c, c}, ss = {s, s};
            *(float2*)&g_pd[(j0 + jl) * (2 * ODIM) + 2 * (i0 + il)] = cc;
            *(float2*)&g_qd[(j0 + jl) * (2 * ODIM) + 2 * (i0 + il)] = ss;
        }
    }
}

// quad-j combine: acc += (s01*m23 + s23*m01) * rcp(m01*m23)
#define QCOMB(ACC, D0, D1, D2, D3)                                      \
    do {                                                                \
        u64 s01 = add2(D0, D1), m01 = mul2(D0, D1);                     \
        u64 s23 = add2(D2, D3), m23 = mul2(D2, D3);                     \
        u64 num = fma2(s23, m01, mul2(s01, m23));                       \
        u64 den = mul2(m01, m23);                                       \
        ACC = fma2(num, rcp2(den), ACC);                                \
    } while (0)

// ---------- main: BM=32 x BN=32 tiles, 64 threads, 8b(4 slots) x 2i/thread --
// grid = 512 blocks (8 i-tiles x 64 b-tiles), 8 CTAs/SM.
__global__ __launch_bounds__(64, 8) void photonic_main(float* __restrict__ out,
                                                       float C2, float D) {
    __shared__ float su[2][16][32];
    __shared__ float sv[2][16][32];
    __shared__ float spd[2][16][64];
    __shared__ float sqd[2][16][64];

    const int tid = threadIdx.x;
    const int bg = tid & 3;    // 4 b-groups x 8 b
    const int ig = tid >> 2;   // 16 i-groups x 2 i
    const int i0 = (blockIdx.x & 7) * 32;
    const int b0 = (blockIdx.x >> 3) * 32;

    const u64 C22 = pack2(C2, C2);
    u64 acc[4][2];
#pragma unroll
    for (int s = 0; s < 4; s++) {
        acc[s][0] = 0ull;
        acc[s][1] = 0ull;
    }

    auto cp_chunk = [&](int kc, int bf) {
        const int j0 = kc * 16;
        // su/sv: 512 floats each -> 2 x 16B per thread
#pragma unroll
        for (int k = 0; k < 2; k++) {
            int idx = tid + 64 * k;
            int r = idx >> 3, c = (idx & 7) * 4;
            cpasync16((u32)__cvta_generic_to_shared(&su[bf][r][c]),
                      g_u + (size_t)(j0 + r) * BDIM + b0 + c);
            cpasync16((u32)__cvta_generic_to_shared(&sv[bf][r][c]),
                      g_v + (size_t)(j0 + r) * BDIM + b0 + c);
        }
        // spd/sqd: 1024 floats each -> 4 x 16B per thread
#pragma unroll
        for (int k = 0; k < 4; k++) {
            int idx = tid + 64 * k;
            int r = idx >> 4, c = (idx & 15) * 4;
            cpasync16((u32)__cvta_generic_to_shared(&spd[bf][r][c]),
                      g_pd + (size_t)(j0 + r) * (2 * ODIM) + 2 * i0 + c);
            cpasync16((u32)__cvta_generic_to_shared(&sqd[bf][r][c]),
                      g_qd + (size_t)(j0 + r) * (2 * ODIM) + 2 * i0 + c);
        }
        CP_COMMIT();
    };

    cp_chunk(0, 0);

    const int NCH = IDIM / 16;  // 16
    for (int c = 0; c < NCH; c++) {
        const int bf = c & 1;
        if (c + 1 < NCH) {
            cp_chunk(c + 1, bf ^ 1);
            CP_WAIT(1);
        } else {
            CP_WAIT(0);
        }
        __syncthreads();

#pragma unroll
        for (int jj = 0; jj < 16; jj += 4) {
            // P/Q: dup pairs, .x = i-sub 0, .y = i-sub 1
            u64 P0[4], P1[4], Q0[4], Q1[4];
#pragma unroll
            for (int k = 0; k < 4; k++) {
                ulonglong2 t = *(const ulonglong2*)&spd[bf][jj + k][ig * 4];
                P0[k] = t.x;
                P1[k] = t.y;
                t = *(const ulonglong2*)&sqd[bf][jj + k][ig * 4];
                Q0[k] = t.x;
                Q1[k] = t.y;
            }
#pragma unroll
            for (int h = 0; h < 2; h++) {
                u64 Ux[4], Uy[4], Vx[4], Vy[4];
#pragma unroll
                for (int k = 0; k < 4; k++) {
                    ulonglong2 t =
                        *(const ulonglong2*)&su[bf][jj + k][bg * 8 + h * 4];
                    Ux[k] = t.x;
                    Uy[k] = t.y;
                    t = *(const ulonglong2*)&sv[bf][jj + k][bg * 8 + h * 4];
                    Vx[k] = t.x;
                    Vy[k] = t.y;
                }
                {
                    u64 d0 = fma2(Ux[0], P0[0], fma2(Vx[0], Q0[0], C22));
                    u64 d1 = fma2(Ux[1], P0[1], fma2(Vx[1], Q0[1], C22));
                    u64 d2 = fma2(Ux[2], P0[2], fma2(Vx[2], Q0[2], C22));
                    u64 d3 = fma2(Ux[3], P0[3], fma2(Vx[3], Q0[3], C22));
                    QCOMB(acc[h * 2][0], d0, d1, d2, d3);
                }
                {
                    u64 d0 = fma2(Ux[0], P1[0], fma2(Vx[0], Q1[0], C22));
                    u64 d1 = fma2(Ux[1], P1[1], fma2(Vx[1], Q1[1], C22));
                    u64 d2 = fma2(Ux[2], P1[2], fma2(Vx[2], Q1[2], C22));
                    u64 d3 = fma2(Ux[3], P1[3], fma2(Vx[3], Q1[3], C22));
                    QCOMB(acc[h * 2][1], d0, d1, d2, d3);
                }
                {
                    u64 d0 = fma2(Uy[0], P0[0], fma2(Vy[0], Q0[0], C22));
                    u64 d1 = fma2(Uy[1], P0[1], fma2(Vy[1], Q0[1], C22));
                    u64 d2 = fma2(Uy[2], P0[2], fma2(Vy[2], Q0[2], C22));
                    u64 d3 = fma2(Uy[3], P0[3], fma2(Vy[3], Q0[3], C22));
                    QCOMB(acc[h * 2 + 1][0], d0, d1, d2, d3);
                }
                {
                    u64 d0 = fma2(Uy[0], P1[0], fma2(Vy[0], Q1[0], C22));
                    u64 d1 = fma2(Uy[1], P1[1], fma2(Vy[1], Q1[1], C22));
                    u64 d2 = fma2(Uy[2], P1[2], fma2(Vy[2], Q1[2], C22));
                    u64 d3 = fma2(Uy[3], P1[3], fma2(Vy[3], Q1[3], C22));
                    QCOMB(acc[h * 2 + 1][1], d0, d1, d2, d3);
                }
            }
        }

        if (c + 1 < NCH) __syncthreads();
    }

    // Epilogue: slot s covers rows b0 + bg*8 + (s>>1)*4 + (s&1)*2 + {0,1}
    // (lanes lo/hi); i-subs give cols i0 + ig*2 + {0,1}.
    const float base = (float)IDIM;
#pragma unroll
    for (int s = 0; s < 4; s++) {
        float l0, h0, l1, h1;
        unpack2(acc[s][0], l0, h0);
        unpack2(acc[s][1], l1, h1);
        int row = b0 + bg * 8 + (s >> 1) * 4 + (s & 1) * 2;
        float* op = out + (size_t)row * ODIM + i0 + ig * 2;
        float2 r;
        r.x = fmaf(D, l0, base);
        r.y = fmaf(D, l1, base);
        *(float2*)op = r;
        r.x = fmaf(D, h0, base);
        r.y = fmaf(D, h1, base);
        *(float2*)(op + ODIM) = r;
    }
}

extern "C" void kernel_launch(void* const* d_in, const int* in_sizes, int n_in,
                              void* d_out, int out_size) {
    const float* x   = (const float*)d_in[0];  // input_matrix [2048, 256]
    const float* off = (const float*)d_in[1];  // phase_offset [256, 256]
    float* out = (float*)d_out;                // [2048, 256]

    const double PI = 3.14159265358979323846;
    const double RADIUS = 5e-6, KAPPA = 0.1, N_EFF = 3.48, LAMBDA = 1.55e-6,
                 LOSS_A = 0.99;
    double t = sqrt(1.0 - KAPPA);
    double at = LOSS_A * t;
    float K  = (float)(2.0 * at);
    float C2 = (float)(1.0 + at * at);
    float D  = (float)(-(1.0 - t * t) * (1.0 - LOSS_A * LOSS_A));
    float phi0 = (float)fmod(2.0 * PI * N_EFF * (2.0 * PI * RADIUS) / LAMBDA,
                             2.0 * PI);

    prep_all<<<576, 256>>>(x, off, K, phi0);
    photonic_main<<<512, 64>>>(out, C2, D);
}

// round 9
// speedup vs baseline: 2.1643x; 1.0010x over previous
#include <cuda_runtime.h>
#include <math.h>

#define BDIM 2048
#define ODIM 256
#define IDIM 256

typedef unsigned long long u64;
typedef unsigned int u32;

// Scratch. g_u[j][b] = -K*cos(phi0+x[b,j]); g_v[j][b] = K*sin(phi0+x[b,j])
// g_pd[j][2i..2i+1] = dup cos(off[i,j]); g_qd = dup sin(off[i,j])
__device__ float g_u[IDIM * BDIM];
__device__ float g_v[IDIM * BDIM];
__device__ float g_pd[IDIM * 2 * ODIM];
__device__ float g_qd[IDIM * 2 * ODIM];

// ---------- packed f32x2 helpers ----------
__device__ __forceinline__ u64 fma2(u64 a, u64 b, u64 c) {
    u64 d;
    asm("fma.rn.f32x2 %0, %1, %2, %3;" : "=l"(d) : "l"(a), "l"(b), "l"(c));
    return d;
}
__device__ __forceinline__ u64 add2(u64 a, u64 b) {
    u64 d;
    asm("add.rn.f32x2 %0, %1, %2;" : "=l"(d) : "l"(a), "l"(b));
    return d;
}
__device__ __forceinline__ u64 mul2(u64 a, u64 b) {
    u64 d;
    asm("mul.rn.f32x2 %0, %1, %2;" : "=l"(d) : "l"(a), "l"(b));
    return d;
}
__device__ __forceinline__ float frcp(float x) {
    float r;
    asm("rcp.approx.ftz.f32 %0, %1;" : "=f"(r) : "f"(x));
    return r;
}
__device__ __forceinline__ u64 rcp2(u64 x) {
    float lo, hi;
    asm("mov.b64 {%0, %1}, %2;" : "=f"(lo), "=f"(hi) : "l"(x));
    lo = frcp(lo);
    hi = frcp(hi);
    u64 r;
    asm("mov.b64 %0, {%1, %2};" : "=l"(r) : "f"(lo), "f"(hi));
    return r;
}
__device__ __forceinline__ u64 pack2(float lo, float hi) {
    u64 r;
    asm("mov.b64 %0, {%1, %2};" : "=l"(r) : "f"(lo), "f"(hi));
    return r;
}
__device__ __forceinline__ void unpack2(u64 v, float& lo, float& hi) {
    asm("mov.b64 {%0, %1}, %2;" : "=f"(lo), "=f"(hi) : "l"(v));
}

// fire-and-forget vector reduction (REDG.64), sm_90+
__device__ __forceinline__ void redadd2(float* p, float a, float b) {
    asm volatile("red.global.add.v2.f32 [%0], {%1, %2};" ::"l"(p), "f"(a),
                 "f"(b)
                 : "memory");
}

// ---------- cp.async (LDGSTS) ----------
__device__ __forceinline__ void cpasync16(u32 saddr, const void* gptr) {
    asm volatile("cp.async.cg.shared.global [%0], [%1], 16;" ::"r"(saddr),
                 "l"(gptr));
}
#define CP_COMMIT() asm volatile("cp.async.commit_group;" ::: "memory")
#define CP_WAIT(N) asm volatile("cp.async.wait_group %0;" ::"n"(N) : "memory")

// ---------- fused prep: uv transpose (512) + pq dup transpose (64) + init (512)
__global__ void prep_all(const float* __restrict__ x,
                         const float* __restrict__ off,
                         float* __restrict__ out, float K, float phi0) {
    const int bx = blockIdx.x;
    if (bx < 512) {
        __shared__ float tc[32][33];
        __shared__ float ts[32][33];
        const int b0 = (bx >> 3) * 32;
        const int j0 = (bx & 7) * 32;
#pragma unroll
        for (int k = 0; k < 4; k++) {
            int lin = threadIdx.x + k * 256;
            int bl = lin >> 5, jl = lin & 31;
            float s, c;
            __sincosf(phi0 + x[(b0 + bl) * IDIM + j0 + jl], &s, &c);
            tc[jl][bl] = c;
            ts[jl][bl] = s;
        }
        __syncthreads();
#pragma unroll
        for (int k = 0; k < 4; k++) {
            int lin = threadIdx.x + k * 256;
            int jl = lin >> 5, bl = lin & 31;
            g_u[(j0 + jl) * BDIM + b0 + bl] = -K * tc[jl][bl];
            g_v[(j0 + jl) * BDIM + b0 + bl] = K * ts[jl][bl];
        }
    } else if (bx < 576) {
        __shared__ float tc[32][33];
        __shared__ float ts[32][33];
        const int r = bx - 512;
        const int i0 = (r >> 3) * 32;
        const int j0 = (r & 7) * 32;
#pragma unroll
        for (int k = 0; k < 4; k++) {
            int lin = threadIdx.x + k * 256;
            int il = lin >> 5, jl = lin & 31;
            float s, c;
            __sincosf(off[(i0 + il) * IDIM + j0 + jl], &s, &c);
            tc[jl][il] = c;
            ts[jl][il] = s;
        }
        __syncthreads();
#pragma unroll
        for (int k = 0; k < 4; k++) {
            int lin = threadIdx.x + k * 256;
            int jl = lin >> 5, il = lin & 31;
            float c = tc[jl][il], s = ts[jl][il];
            float2 cc = {c, c}, ss = {s, s};
            *(float2*)&g_pd[(j0 + jl) * (2 * ODIM) + 2 * (i0 + il)] = cc;
            *(float2*)&g_qd[(j0 + jl) * (2 * ODIM) + 2 * (i0 + il)] = ss;
        }
    } else {
        // init out = IDIM (base of T-sum); 512 blocks x 256 thr x float4
        int idx = (bx - 576) * 256 + threadIdx.x;
        float4 v = {(float)IDIM, (float)IDIM, (float)IDIM, (float)IDIM};
        ((float4*)out)[idx] = v;
    }
}

// quad-j combine: acc += (s01*m23 + s23*m01) * rcp(m01*m23)
#define QCOMB(ACC, D0, D1, D2, D3)                                      \
    do {                                                                \
        u64 s01 = add2(D0, D1), m01 = mul2(D0, D1);                     \
        u64 s23 = add2(D2, D3), m23 = mul2(D2, D3);                     \
        u64 num = fma2(s23, m01, mul2(s01, m23));                       \
        u64 den = mul2(m01, m23);                                       \
        ACC = fma2(num, rcp2(den), ACC);                                \
    } while (0)

// ---------- main: BM=32 x BN=32 x (IDIM/2) work units, 64 threads ----------
// grid = 1024: bit0 = j-half, bits[1..] = spatial (8 i-tiles x 64 b-tiles).
// Per thread: 8 b (4 packed slots) x 2 i; partial sums flushed via red.v2.
__global__ __launch_bounds__(64, 8) void photonic_main(float* __restrict__ out,
                                                       float C2, float D) {
    __shared__ float su[2][16][32];
    __shared__ float sv[2][16][32];
    __shared__ float spd[2][16][64];
    __shared__ float sqd[2][16][64];

    const int tid = threadIdx.x;
    const int bg = tid & 3;    // 4 b-groups x 8 b
    const int ig = tid >> 2;   // 16 i-groups x 2 i
    const int kh = blockIdx.x & 1;           // j-half
    const int spat = blockIdx.x >> 1;        // 0..511
    const int i0 = (spat & 7) * 32;
    const int b0 = (spat >> 3) * 32;
    const int jbase = kh * (IDIM / 2);

    const u64 C22 = pack2(C2, C2);
    u64 acc[4][2];
#pragma unroll
    for (int s = 0; s < 4; s++) {
        acc[s][0] = 0ull;
        acc[s][1] = 0ull;
    }

    auto cp_chunk = [&](int kc, int bf) {
        const int j0 = jbase + kc * 16;
#pragma unroll
        for (int k = 0; k < 2; k++) {
            int idx = tid + 64 * k;
            int r = idx >> 3, c = (idx & 7) * 4;
            cpasync16((u32)__cvta_generic_to_shared(&su[bf][r][c]),
                      g_u + (size_t)(j0 + r) * BDIM + b0 + c);
            cpasync16((u32)__cvta_generic_to_shared(&sv[bf][r][c]),
                      g_v + (size_t)(j0 + r) * BDIM + b0 + c);
        }
#pragma unroll
        for (int k = 0; k < 4; k++) {
            int idx = tid + 64 * k;
            int r = idx >> 4, c = (idx & 15) * 4;
            cpasync16((u32)__cvta_generic_to_shared(&spd[bf][r][c]),
                      g_pd + (size_t)(j0 + r) * (2 * ODIM) + 2 * i0 + c);
            cpasync16((u32)__cvta_generic_to_shared(&sqd[bf][r][c]),
                      g_qd + (size_t)(j0 + r) * (2 * ODIM) + 2 * i0 + c);
        }
        CP_COMMIT();
    };

    cp_chunk(0, 0);

    const int NCH = (IDIM / 2) / 16;  // 8
    for (int c = 0; c < NCH; c++) {
        const int bf = c & 1;
        if (c + 1 < NCH) {
            cp_chunk(c + 1, bf ^ 1);
            CP_WAIT(1);
        } else {
            CP_WAIT(0);
        }
        __syncthreads();

#pragma unroll
        for (int jj = 0; jj < 16; jj += 4) {
            u64 P0[4], P1[4], Q0[4], Q1[4];
#pragma unroll
            for (int k = 0; k < 4; k++) {
                ulonglong2 t = *(const ulonglong2*)&spd[bf][jj + k][ig * 4];
                P0[k] = t.x;
                P1[k] = t.y;
                t = *(const ulonglong2*)&sqd[bf][jj + k][ig * 4];
                Q0[k] = t.x;
                Q1[k] = t.y;
            }
#pragma unroll
            for (int h = 0; h < 2; h++) {
                u64 Ux[4], Uy[4], Vx[4], Vy[4];
#pragma unroll
                for (int k = 0; k < 4; k++) {
                    ulonglong2 t =
                        *(const ulonglong2*)&su[bf][jj + k][bg * 8 + h * 4];
                    Ux[k] = t.x;
                    Uy[k] = t.y;
                    t = *(const ulonglong2*)&sv[bf][jj + k][bg * 8 + h * 4];
                    Vx[k] = t.x;
                    Vy[k] = t.y;
                }
                {
                    u64 d0 = fma2(Ux[0], P0[0], fma2(Vx[0], Q0[0], C22));
                    u64 d1 = fma2(Ux[1], P0[1], fma2(Vx[1], Q0[1], C22));
                    u64 d2 = fma2(Ux[2], P0[2], fma2(Vx[2], Q0[2], C22));
                    u64 d3 = fma2(Ux[3], P0[3], fma2(Vx[3], Q0[3], C22));
                    QCOMB(acc[h * 2][0], d0, d1, d2, d3);
                }
                {
                    u64 d0 = fma2(Ux[0], P1[0], fma2(Vx[0], Q1[0], C22));
                    u64 d1 = fma2(Ux[1], P1[1], fma2(Vx[1], Q1[1], C22));
                    u64 d2 = fma2(Ux[2], P1[2], fma2(Vx[2], Q1[2], C22));
                    u64 d3 = fma2(Ux[3], P1[3], fma2(Vx[3], Q1[3], C22));
                    QCOMB(acc[h * 2][1], d0, d1, d2, d3);
                }
                {
                    u64 d0 = fma2(Uy[0], P0[0], fma2(Vy[0], Q0[0], C22));
                    u64 d1 = fma2(Uy[1], P0[1], fma2(Vy[1], Q0[1], C22));
                    u64 d2 = fma2(Uy[2], P0[2], fma2(Vy[2], Q0[2], C22));
                    u64 d3 = fma2(Uy[3], P0[3], fma2(Vy[3], Q0[3], C22));
                    QCOMB(acc[h * 2 + 1][0], d0, d1, d2, d3);
                }
                {
                    u64 d0 = fma2(Uy[0], P1[0], fma2(Vy[0], Q1[0], C22));
                    u64 d1 = fma2(Uy[1], P1[1], fma2(Vy[1], Q1[1], C22));
                    u64 d2 = fma2(Uy[2], P1[2], fma2(Vy[2], Q1[2], C22));
                    u64 d3 = fma2(Uy[3], P1[3], fma2(Vy[3], Q1[3], C22));
                    QCOMB(acc[h * 2 + 1][1], d0, d1, d2, d3);
                }
            }
        }

        if (c + 1 < NCH) __syncthreads();
    }

    // Flush partial sums: slot s covers rows b0 + bg*8 + (s>>1)*4 + (s&1)*2
    // + {0,1} (lanes lo/hi); cols i0 + ig*2 + {0,1} via red.v2.
#pragma unroll
    for (int s = 0; s < 4; s++) {
        float l0, h0, l1, h1;
        unpack2(acc[s][0], l0, h0);
        unpack2(acc[s][1], l1, h1);
        int row = b0 + bg * 8 + (s >> 1) * 4 + (s & 1) * 2;
        float* op = out + (size_t)row * ODIM + i0 + ig * 2;
        redadd2(op, D * l0, D * l1);
        redadd2(op + ODIM, D * h0, D * h1);
    }
}

extern "C" void kernel_launch(void* const* d_in, const int* in_sizes, int n_in,
                              void* d_out, int out_size) {
    const float* x   = (const float*)d_in[0];  // input_matrix [2048, 256]
    const float* off = (const float*)d_in[1];  // phase_offset [256, 256]
    float* out = (float*)d_out;                // [2048, 256]

    const double PI = 3.14159265358979323846;
    const double RADIUS = 5e-6, KAPPA = 0.1, N_EFF = 3.48, LAMBDA = 1.55e-6,
                 LOSS_A = 0.99;
    double t = sqrt(1.0 - KAPPA);
    double at = LOSS_A * t;
    float K  = (float)(2.0 * at);
    float C2 = (float)(1.0 + at * at);
    float D  = (float)(-(1.0 - t * t) * (1.0 - LOSS_A * LOSS_A));
    float phi0 = (float)fmod(2.0 * PI * N_EFF * (2.0 * PI * RADIUS) / LAMBDA,
                             2.0 * PI);

    prep_all<<<1088, 256>>>(x, off, out, K, phi0);
    photonic_main<<<1024, 64>>>(out, C2, D);
}

// round 10
// speedup vs baseline: 2.3979x; 1.1079x over previous
#include <cuda_runtime.h>
#include <math.h>

#define BDIM 2048
#define ODIM 256
#define IDIM 256

typedef unsigned long long u64;
typedef unsigned int u32;

// Scratch. g_u[j][b] = -K*cos(phi0+x[b,j]); g_v[j][b] = K*sin(phi0+x[b,j])
// g_p[j][i] = cos(off[i,j]); g_q[j][i] = sin(off[i,j])   (scalar, non-dup)
__device__ float g_u[IDIM * BDIM];
__device__ float g_v[IDIM * BDIM];
__device__ float g_p[IDIM * ODIM];
__device__ float g_q[IDIM * ODIM];

// ---------- packed f32x2 helpers ----------
__device__ __forceinline__ u64 fma2(u64 a, u64 b, u64 c) {
    u64 d;
    asm("fma.rn.f32x2 %0, %1, %2, %3;" : "=l"(d) : "l"(a), "l"(b), "l"(c));
    return d;
}
__device__ __forceinline__ u64 add2(u64 a, u64 b) {
    u64 d;
    asm("add.rn.f32x2 %0, %1, %2;" : "=l"(d) : "l"(a), "l"(b));
    return d;
}
__device__ __forceinline__ u64 mul2(u64 a, u64 b) {
    u64 d;
    asm("mul.rn.f32x2 %0, %1, %2;" : "=l"(d) : "l"(a), "l"(b));
    return d;
}
__device__ __forceinline__ float frcp(float x) {
    float r;
    asm("rcp.approx.ftz.f32 %0, %1;" : "=f"(r) : "f"(x));
    return r;
}
__device__ __forceinline__ u64 rcp2(u64 x) {
    float lo, hi;
    asm("mov.b64 {%0, %1}, %2;" : "=f"(lo), "=f"(hi) : "l"(x));
    lo = frcp(lo);
    hi = frcp(hi);
    u64 r;
    asm("mov.b64 %0, {%1, %2};" : "=l"(r) : "f"(lo), "f"(hi));
    return r;
}
__device__ __forceinline__ u64 pack2(float lo, float hi) {
    u64 r;
    asm("mov.b64 %0, {%1, %2};" : "=l"(r) : "f"(lo), "f"(hi));
    return r;
}
__device__ __forceinline__ void unpack2(u64 v, float& lo, float& hi) {
    asm("mov.b64 {%0, %1}, %2;" : "=f"(lo), "=f"(hi) : "l"(v));
}

// fire-and-forget vector reduction (REDG.64), sm_90+
__device__ __forceinline__ void redadd2(float* p, float a, float b) {
    asm volatile("red.global.add.v2.f32 [%0], {%1, %2};" ::"l"(p), "f"(a),
                 "f"(b)
                 : "memory");
}

// ---------- cp.async (LDGSTS) ----------
__device__ __forceinline__ void cpasync16(u32 saddr, const void* gptr) {
    asm volatile("cp.async.cg.shared.global [%0], [%1], 16;" ::"r"(saddr),
                 "l"(gptr));
}
#define CP_COMMIT() asm volatile("cp.async.commit_group;" ::: "memory")
#define CP_WAIT(N) asm volatile("cp.async.wait_group %0;" ::"n"(N) : "memory")

// ---------- fused prep: uv transpose (512) + pq transpose (64) + init (512)
__global__ void prep_all(const float* __restrict__ x,
                         const float* __restrict__ off,
                         float* __restrict__ out, float K, float phi0) {
    const int bx = blockIdx.x;
    if (bx < 512) {
        __shared__ float tc[32][33];
        __shared__ float ts[32][33];
        const int b0 = (bx >> 3) * 32;
        const int j0 = (bx & 7) * 32;
#pragma unroll
        for (int k = 0; k < 4; k++) {
            int lin = threadIdx.x + k * 256;
            int bl = lin >> 5, jl = lin & 31;
            float s, c;
            __sincosf(phi0 + x[(b0 + bl) * IDIM + j0 + jl], &s, &c);
            tc[jl][bl] = c;
            ts[jl][bl] = s;
        }
        __syncthreads();
#pragma unroll
        for (int k = 0; k < 4; k++) {
            int lin = threadIdx.x + k * 256;
            int jl = lin >> 5, bl = lin & 31;
            g_u[(j0 + jl) * BDIM + b0 + bl] = -K * tc[jl][bl];
            g_v[(j0 + jl) * BDIM + b0 + bl] = K * ts[jl][bl];
        }
    } else if (bx < 576) {
        __shared__ float tc[32][33];
        __shared__ float ts[32][33];
        const int r = bx - 512;
        const int i0 = (r >> 3) * 32;
        const int j0 = (r & 7) * 32;
#pragma unroll
        for (int k = 0; k < 4; k++) {
            int lin = threadIdx.x + k * 256;
            int il = lin >> 5, jl = lin & 31;
            float s, c;
            __sincosf(off[(i0 + il) * IDIM + j0 + jl], &s, &c);
            tc[jl][il] = c;
            ts[jl][il] = s;
        }
        __syncthreads();
#pragma unroll
        for (int k = 0; k < 4; k++) {
            int lin = threadIdx.x + k * 256;
            int jl = lin >> 5, il = lin & 31;
            g_p[(j0 + jl) * ODIM + i0 + il] = tc[jl][il];
            g_q[(j0 + jl) * ODIM + i0 + il] = ts[jl][il];
        }
    } else {
        // init out = IDIM (base of T-sum); 512 blocks x 256 thr x float4
        int idx = (bx - 576) * 256 + threadIdx.x;
        float4 v = {(float)IDIM, (float)IDIM, (float)IDIM, (float)IDIM};
        ((float4*)out)[idx] = v;
    }
}

// quad-j combine: acc += (s01*m23 + s23*m01) * rcp(m01*m23)
#define QCOMB(ACC, D0, D1, D2, D3)                                      \
    do {                                                                \
        u64 s01 = add2(D0, D1), m01 = mul2(D0, D1);                     \
        u64 s23 = add2(D2, D3), m23 = mul2(D2, D3);                     \
        u64 num = fma2(s23, m01, mul2(s01, m23));                       \
        u64 den = mul2(m01, m23);                                       \
        ACC = fma2(num, rcp2(den), ACC);                                \
    } while (0)

// ---------- main: BM=32 x BN=64 x 64j work units, 64 threads ---------------
// grid = 1024: bits[0:1] = k-part (64 j), bits[2..] = spatial (4 i x 64 b).
// Per thread: 8 b (4 packed slots) x 4 i -> 16 packed accumulators.
__global__ __launch_bounds__(64, 6) void photonic_main(float* __restrict__ out,
                                                       float C2, float D) {
    __shared__ float su[2][16][32];
    __shared__ float sv[2][16][32];
    __shared__ float sp[2][16][64];
    __shared__ float sq[2][16][64];

    const int tid = threadIdx.x;
    const int bg = tid & 3;    // 4 b-groups x 8 b
    const int ig = tid >> 2;   // 16 i-groups x 4 i
    const int kpart = blockIdx.x & 3;
    const int spat = blockIdx.x >> 2;  // 0..255
    const int i0 = (spat & 3) * 64;
    const int b0 = (spat >> 2) * 32;
    const int jbase = kpart * 64;

    const u64 C22 = pack2(C2, C2);
    u64 acc[4][4];  // [b-slot][i]
#pragma unroll
    for (int s = 0; s < 4; s++)
#pragma unroll
        for (int i = 0; i < 4; i++) acc[s][i] = 0ull;

    auto cp_chunk = [&](int kc, int bf) {
        const int j0 = jbase + kc * 16;
#pragma unroll
        for (int k = 0; k < 2; k++) {
            int idx = tid + 64 * k;
            int r = idx >> 3, c = (idx & 7) * 4;
            cpasync16((u32)__cvta_generic_to_shared(&su[bf][r][c]),
                      g_u + (size_t)(j0 + r) * BDIM + b0 + c);
            cpasync16((u32)__cvta_generic_to_shared(&sv[bf][r][c]),
                      g_v + (size_t)(j0 + r) * BDIM + b0 + c);
        }
#pragma unroll
        for (int k = 0; k < 4; k++) {
            int idx = tid + 64 * k;
            int r = idx >> 4, c = (idx & 15) * 4;
            cpasync16((u32)__cvta_generic_to_shared(&sp[bf][r][c]),
                      g_p + (size_t)(j0 + r) * ODIM + i0 + c);
            cpasync16((u32)__cvta_generic_to_shared(&sq[bf][r][c]),
                      g_q + (size_t)(j0 + r) * ODIM + i0 + c);
        }
        CP_COMMIT();
    };

    cp_chunk(0, 0);

    const int NCH = 4;  // 64 j / 16
    for (int c = 0; c < NCH; c++) {
        const int bf = c & 1;
        if (c + 1 < NCH) {
            cp_chunk(c + 1, bf ^ 1);
            CP_WAIT(1);
        } else {
            CP_WAIT(0);
        }
        __syncthreads();

#pragma unroll
        for (int jj = 0; jj < 16; jj += 4) {
            // scalar P/Q for this thread's 4 i, all 4 k
            float4 p4[4], q4[4];
#pragma unroll
            for (int k = 0; k < 4; k++) {
                p4[k] = *(const float4*)&sp[bf][jj + k][ig * 4];
                q4[k] = *(const float4*)&sq[bf][jj + k][ig * 4];
            }
#pragma unroll
            for (int h = 0; h < 2; h++) {
                // U/V for b-slots 2h, 2h+1 (4 b)
                u64 Ux[4], Uy[4], Vx[4], Vy[4];
#pragma unroll
                for (int k = 0; k < 4; k++) {
                    ulonglong2 t =
                        *(const ulonglong2*)&su[bf][jj + k][bg * 8 + h * 4];
                    Ux[k] = t.x;
                    Uy[k] = t.y;
                    t = *(const ulonglong2*)&sv[bf][jj + k][bg * 8 + h * 4];
                    Vx[k] = t.x;
                    Vy[k] = t.y;
                }
#pragma unroll
                for (int i = 0; i < 4; i++) {
                    float pv0 = (i == 0) ? p4[0].x : (i == 1) ? p4[0].y : (i == 2) ? p4[0].z : p4[0].w;
                    float pv1 = (i == 0) ? p4[1].x : (i == 1) ? p4[1].y : (i == 2) ? p4[1].z : p4[1].w;
                    float pv2 = (i == 0) ? p4[2].x : (i == 1) ? p4[2].y : (i == 2) ? p4[2].z : p4[2].w;
                    float pv3 = (i == 0) ? p4[3].x : (i == 1) ? p4[3].y : (i == 2) ? p4[3].z : p4[3].w;
                    float qv0 = (i == 0) ? q4[0].x : (i == 1) ? q4[0].y : (i == 2) ? q4[0].z : q4[0].w;
                    float qv1 = (i == 0) ? q4[1].x : (i == 1) ? q4[1].y : (i == 2) ? q4[1].z : q4[1].w;
                    float qv2 = (i == 0) ? q4[2].x : (i == 1) ? q4[2].y : (i == 2) ? q4[2].z : q4[2].w;
                    float qv3 = (i == 0) ? q4[3].x : (i == 1) ? q4[3].y : (i == 2) ? q4[3].z : q4[3].w;
                    u64 P0 = pack2(pv0, pv0), P1 = pack2(pv1, pv1);
                    u64 P2 = pack2(pv2, pv2), P3 = pack2(pv3, pv3);
                    u64 Q0 = pack2(qv0, qv0), Q1 = pack2(qv1, qv1);
                    u64 Q2 = pack2(qv2, qv2), Q3 = pack2(qv3, qv3);
                    {
                        u64 d0 = fma2(Ux[0], P0, fma2(Vx[0], Q0, C22));
                        u64 d1 = fma2(Ux[1], P1, fma2(Vx[1], Q1, C22));
                        u64 d2 = fma2(Ux[2], P2, fma2(Vx[2], Q2, C22));
                        u64 d3 = fma2(Ux[3], P3, fma2(Vx[3], Q3, C22));
                        QCOMB(acc[h * 2][i], d0, d1, d2, d3);
                    }
                    {
                        u64 d0 = fma2(Uy[0], P0, fma2(Vy[0], Q0, C22));
                        u64 d1 = fma2(Uy[1], P1, fma2(Vy[1], Q1, C22));
                        u64 d2 = fma2(Uy[2], P2, fma2(Vy[2], Q2, C22));
                        u64 d3 = fma2(Uy[3], P3, fma2(Vy[3], Q3, C22));
                        QCOMB(acc[h * 2 + 1][i], d0, d1, d2, d3);
                    }
                }
            }
        }

        if (c + 1 < NCH) __syncthreads();
    }

    // Flush: slot s -> rows b0 + bg*8 + 2s + {0,1} (lanes lo/hi);
    // cols i0 + ig*4 + {0..3}; partial sums via red.v2 along i.
#pragma unroll
    for (int s = 0; s < 4; s++) {
        float l[4], h[4];
#pragma unroll
        for (int i = 0; i < 4; i++) unpack2(acc[s][i], l[i], h[i]);
        int row = b0 + bg * 8 + 2 * s;
        float* op = out + (size_t)row * ODIM + i0 + ig * 4;
        redadd2(op, D * l[0], D * l[1]);
        redadd2(op + 2, D * l[2], D * l[3]);
        redadd2(op + ODIM, D * h[0], D * h[1]);
        redadd2(op + ODIM + 2, D * h[2], D * h[3]);
    }
}

extern "C" void kernel_launch(void* const* d_in, const int* in_sizes, int n_in,
                              void* d_out, int out_size) {
    const float* x   = (const float*)d_in[0];  // input_matrix [2048, 256]
    const float* off = (const float*)d_in[1];  // phase_offset [256, 256]
    float* out = (float*)d_out;                // [2048, 256]

    const double PI = 3.14159265358979323846;
    const double RADIUS = 5e-6, KAPPA = 0.1, N_EFF = 3.48, LAMBDA = 1.55e-6,
                 LOSS_A = 0.99;
    double t = sqrt(1.0 - KAPPA);
    double at = LOSS_A * t;
    float K  = (float)(2.0 * at);
    float C2 = (float)(1.0 + at * at);
    float D  = (float)(-(1.0 - t * t) * (1.0 - LOSS_A * LOSS_A));
    float phi0 = (float)fmod(2.0 * PI * N_EFF * (2.0 * PI * RADIUS) / LAMBDA,
                             2.0 * PI);

    prep_all<<<1088, 256>>>(x, off, out, K, phi0);
    photonic_main<<<1024, 64>>>(out, C2, D);
}

// round 12
// speedup vs baseline: 2.4657x; 1.0283x over previous
#include <cuda_runtime.h>
#include <math.h>

#define BDIM 2048
#define ODIM 256
#define IDIM 256

typedef unsigned long long u64;
typedef unsigned int u32;

// Scratch. g_u[j][b] = -K*cos(phi0+x[b,j]); g_v[j][b] = K*sin(phi0+x[b,j])
// g_p[j][i] = cos(off[i,j]); g_q[j][i] = sin(off[i,j])
__device__ float g_u[IDIM * BDIM];
__device__ float g_v[IDIM * BDIM];
__device__ float g_p[IDIM * ODIM];
__device__ float g_q[IDIM * ODIM];

// ---------- packed f32x2 helpers ----------
__device__ __forceinline__ u64 fma2(u64 a, u64 b, u64 c) {
    u64 d;
    asm("fma.rn.f32x2 %0, %1, %2, %3;" : "=l"(d) : "l"(a), "l"(b), "l"(c));
    return d;
}
__device__ __forceinline__ u64 add2(u64 a, u64 b) {
    u64 d;
    asm("add.rn.f32x2 %0, %1, %2;" : "=l"(d) : "l"(a), "l"(b));
    return d;
}
__device__ __forceinline__ u64 mul2(u64 a, u64 b) {
    u64 d;
    asm("mul.rn.f32x2 %0, %1, %2;" : "=l"(d) : "l"(a), "l"(b));
    return d;
}
__device__ __forceinline__ float frcp(float x) {
    float r;
    asm("rcp.approx.ftz.f32 %0, %1;" : "=f"(r) : "f"(x));
    return r;
}
__device__ __forceinline__ u64 rcp2(u64 x) {
    float lo, hi;
    asm("mov.b64 {%0, %1}, %2;" : "=f"(lo), "=f"(hi) : "l"(x));
    lo = frcp(lo);
    hi = frcp(hi);
    u64 r;
    asm("mov.b64 %0, {%1, %2};" : "=l"(r) : "f"(lo), "f"(hi));
    return r;
}
__device__ __forceinline__ u64 pack2(float lo, float hi) {
    u64 r;
    asm("mov.b64 %0, {%1, %2};" : "=l"(r) : "f"(lo), "f"(hi));
    return r;
}
__device__ __forceinline__ void unpack2(u64 v, float& lo, float& hi) {
    asm("mov.b64 {%0, %1}, %2;" : "=f"(lo), "=f"(hi) : "l"(v));
}

// fire-and-forget vector reduction (REDG.64), sm_90+
__device__ __forceinline__ void redadd2(float* p, float a, float b) {
    asm volatile("red.global.add.v2.f32 [%0], {%1, %2};" ::"l"(p), "f"(a),
                 "f"(b)
                 : "memory");
}

// ---------- cp.async (LDGSTS) ----------
__device__ __forceinline__ void cpasync16(u32 saddr, const void* gptr) {
    asm volatile("cp.async.cg.shared.global [%0], [%1], 16;" ::"r"(saddr),
                 "l"(gptr));
}
#define CP_COMMIT() asm volatile("cp.async.commit_group;" ::: "memory")
#define CP_WAIT(N) asm volatile("cp.async.wait_group %0;" ::"n"(N) : "memory")

// ---------- fused prep: uv transpose (512) + pq transpose (64) + init (512)
__global__ void prep_all(const float* __restrict__ x,
                         const float* __restrict__ off,
                         float* __restrict__ out, float K, float phi0) {
    const int bx = blockIdx.x;
    if (bx < 512) {
        __shared__ float tc[32][33];
        __shared__ float ts[32][33];
        const int b0 = (bx >> 3) * 32;
        const int j0 = (bx & 7) * 32;
#pragma unroll
        for (int k = 0; k < 4; k++) {
            int lin = threadIdx.x + k * 256;
            int bl = lin >> 5, jl = lin & 31;
            float s, c;
            __sincosf(phi0 + x[(b0 + bl) * IDIM + j0 + jl], &s, &c);
            tc[jl][bl] = c;
            ts[jl][bl] = s;
        }
        __syncthreads();
#pragma unroll
        for (int k = 0; k < 4; k++) {
            int lin = threadIdx.x + k * 256;
            int jl = lin >> 5, bl = lin & 31;
            g_u[(j0 + jl) * BDIM + b0 + bl] = -K * tc[jl][bl];
            g_v[(j0 + jl) * BDIM + b0 + bl] = K * ts[jl][bl];
        }
    } else if (bx < 576) {
        __shared__ float tc[32][33];
        __shared__ float ts[32][33];
        const int r = bx - 512;
        const int i0 = (r >> 3) * 32;
        const int j0 = (r & 7) * 32;
#pragma unroll
        for (int k = 0; k < 4; k++) {
            int lin = threadIdx.x + k * 256;
            int il = lin >> 5, jl = lin & 31;
            float s, c;
            __sincosf(off[(i0 + il) * IDIM + j0 + jl], &s, &c);
            tc[jl][il] = c;
            ts[jl][il] = s;
        }
        __syncthreads();
#pragma unroll
        for (int k = 0; k < 4; k++) {
            int lin = threadIdx.x + k * 256;
            int jl = lin >> 5, il = lin & 31;
            g_p[(j0 + jl) * ODIM + i0 + il] = tc[jl][il];
            g_q[(j0 + jl) * ODIM + i0 + il] = ts[jl][il];
        }
    } else {
        // init out = IDIM (base of T-sum); 512 blocks x 256 thr x float4
        int idx = (bx - 576) * 256 + threadIdx.x;
        float4 v = {(float)IDIM, (float)IDIM, (float)IDIM, (float)IDIM};
        ((float4*)out)[idx] = v;
    }
}

// quad-j combine: acc += (s01*m23 + s23*m01) * rcp(m01*m23)
#define QCOMB(ACC, D0, D1, D2, D3)                                      \
    do {                                                                \
        u64 s01 = add2(D0, D1), m01 = mul2(D0, D1);                     \
        u64 s23 = add2(D2, D3), m23 = mul2(D2, D3);                     \
        u64 num = fma2(s23, m01, mul2(s01, m23));                       \
        u64 den = mul2(m01, m23);                                       \
        ACC = fma2(num, rcp2(den), ACC);                                \
    } while (0)

// ---------- main: BM=32 x BN=64 x 32j work units, 128 threads --------------
// grid = 2048: bits[0:2] = k-part (32 j), bits[3..] = spatial (4 i x 64 b).
// Per thread: 4 b (2 packed slots) x 4 i -> 8 packed accumulators.
__global__ __launch_bounds__(128, 4) void photonic_main(float* __restrict__ out,
                                                        float C2, float D) {
    __shared__ float su[2][16][32];
    __shared__ float sv[2][16][32];
    __shared__ float sp[2][16][64];
    __shared__ float sq[2][16][64];

    const int tid = threadIdx.x;
    const int bg = tid & 7;    // 8 b-groups x 4 b
    const int ig = tid >> 3;   // 16 i-groups x 4 i
    const int kpart = blockIdx.x & 7;
    const int spat = blockIdx.x >> 3;  // 0..255
    const int i0 = (spat & 3) * 64;
    const int b0 = (spat >> 2) * 32;
    const int jbase = kpart * 32;

    const u64 C22 = pack2(C2, C2);
    u64 acc[2][4];  // [b-slot][i]
#pragma unroll
    for (int s = 0; s < 2; s++)
#pragma unroll
        for (int i = 0; i < 4; i++) acc[s][i] = 0ull;

    auto cp_chunk = [&](int kc, int bf) {
        const int j0 = jbase + kc * 16;
        // su/sv: 512 floats each -> 1 x 16B per thread
        {
            int r = tid >> 3, c = (tid & 7) * 4;
            cpasync16((u32)__cvta_generic_to_shared(&su[bf][r][c]),
                      g_u + (size_t)(j0 + r) * BDIM + b0 + c);
            cpasync16((u32)__cvta_generic_to_shared(&sv[bf][r][c]),
                      g_v + (size_t)(j0 + r) * BDIM + b0 + c);
        }
        // sp/sq: 1024 floats each -> 2 x 16B per thread
#pragma unroll
        for (int k = 0; k < 2; k++) {
            int idx = tid + 128 * k;
            int r = idx >> 4, c = (idx & 15) * 4;
            cpasync16((u32)__cvta_generic_to_shared(&sp[bf][r][c]),
                      g_p + (size_t)(j0 + r) * ODIM + i0 + c);
            cpasync16((u32)__cvta_generic_to_shared(&sq[bf][r][c]),
                      g_q + (size_t)(j0 + r) * ODIM + i0 + c);
        }
        CP_COMMIT();
    };

    cp_chunk(0, 0);

    const int NCH = 2;  // 32 j / 16
    for (int c = 0; c < NCH; c++) {
        const int bf = c & 1;
        if (c + 1 < NCH) {
            cp_chunk(c + 1, bf ^ 1);
            CP_WAIT(1);
        } else {
            CP_WAIT(0);
        }
        __syncthreads();

#pragma unroll
        for (int jj = 0; jj < 16; jj += 4) {
            // U/V for both slots (4 b), all 4 k of this j-group
            u64 Ux[4], Uy[4], Vx[4], Vy[4];
#pragma unroll
            for (int k = 0; k < 4; k++) {
                ulonglong2 t = *(const ulonglong2*)&su[bf][jj + k][bg * 4];
                Ux[k] = t.x;
                Uy[k] = t.y;
                t = *(const ulonglong2*)&sv[bf][jj + k][bg * 4];
                Vx[k] = t.x;
                Vy[k] = t.y;
            }
            // scalar P/Q for this thread's 4 i, all 4 k
            float4 p4[4], q4[4];
#pragma unroll
            for (int k = 0; k < 4; k++) {
                p4[k] = *(const float4*)&sp[bf][jj + k][ig * 4];
                q4[k] = *(const float4*)&sq[bf][jj + k][ig * 4];
            }
#pragma unroll
            for (int i = 0; i < 4; i++) {
                float pv0 = (i == 0) ? p4[0].x : (i == 1) ? p4[0].y : (i == 2) ? p4[0].z : p4[0].w;
                float pv1 = (i == 0) ? p4[1].x : (i == 1) ? p4[1].y : (i == 2) ? p4[1].z : p4[1].w;
                float pv2 = (i == 0) ? p4[2].x : (i == 1) ? p4[2].y : (i == 2) ? p4[2].z : p4[2].w;
                float pv3 = (i == 0) ? p4[3].x : (i == 1) ? p4[3].y : (i == 2) ? p4[3].z : p4[3].w;
                float qv0 = (i == 0) ? q4[0].x : (i == 1) ? q4[0].y : (i == 2) ? q4[0].z : q4[0].w;
                float qv1 = (i == 0) ? q4[1].x : (i == 1) ? q4[1].y : (i == 2) ? q4[1].z : q4[1].w;
                float qv2 = (i == 0) ? q4[2].x : (i == 1) ? q4[2].y : (i == 2) ? q4[2].z : q4[2].w;
                float qv3 = (i == 0) ? q4[3].x : (i == 1) ? q4[3].y : (i == 2) ? q4[3].z : q4[3].w;
                u64 P0 = pack2(pv0, pv0), P1 = pack2(pv1, pv1);
                u64 P2 = pack2(pv2, pv2), P3 = pack2(pv3, pv3);
                u64 Q0 = pack2(qv0, qv0), Q1 = pack2(qv1, qv1);
                u64 Q2 = pack2(qv2, qv2), Q3 = pack2(qv3, qv3);
                {
                    u64 d0 = fma2(Ux[0], P0, fma2(Vx[0], Q0, C22));
                    u64 d1 = fma2(Ux[1], P1, fma2(Vx[1], Q1, C22));
                    u64 d2 = fma2(Ux[2], P2, fma2(Vx[2], Q2, C22));
                    u64 d3 = fma2(Ux[3], P3, fma2(Vx[3], Q3, C22));
                    QCOMB(acc[0][i], d0, d1, d2, d3);
                }
                {
                    u64 d0 = fma2(Uy[0], P0, fma2(Vy[0], Q0, C22));
                    u64 d1 = fma2(Uy[1], P1, fma2(Vy[1], Q1, C22));
                    u64 d2 = fma2(Uy[2], P2, fma2(Vy[2], Q2, C22));
                    u64 d3 = fma2(Uy[3], P3, fma2(Vy[3], Q3, C22));
                    QCOMB(acc[1][i], d0, d1, d2, d3);
                }
            }
        }

        if (c + 1 < NCH) __syncthreads();
    }

    // Flush: slot s -> rows b0 + bg*4 + 2s + {0,1} (lanes lo/hi);
    // cols i0 + ig*4 + {0..3}; partial sums via red.v2 along i.
#pragma unroll
    for (int s = 0; s < 2; s++) {
        float l[4], h[4];
#pragma unroll
        for (int i = 0; i < 4; i++) unpack2(acc[s][i], l[i], h[i]);
        int row = b0 + bg * 4 + 2 * s;
        float* op = out + (size_t)row * ODIM + i0 + ig * 4;
        redadd2(op, D * l[0], D * l[1]);
        redadd2(op + 2, D * l[2], D * l[3]);
        redadd2(op + ODIM, D * h[0], D * h[1]);
        redadd2(op + ODIM + 2, D * h[2], D * h[3]);
    }
}

extern "C" void kernel_launch(void* const* d_in, const int* in_sizes, int n_in,
                              void* d_out, int out_size) {
    const float* x   = (const float*)d_in[0];  // input_matrix [2048, 256]
    const float* off = (const float*)d_in[1];  // phase_offset [256, 256]
    float* out = (float*)d_out;                // [2048, 256]

    const double PI = 3.14159265358979323846;
    const double RADIUS = 5e-6, KAPPA = 0.1, N_EFF = 3.48, LAMBDA = 1.55e-6,
                 LOSS_A = 0.99;
    double t = sqrt(1.0 - KAPPA);
    double at = LOSS_A * t;
    float K  = (float)(2.0 * at);
    float C2 = (float)(1.0 + at * at);
    float D  = (float)(-(1.0 - t * t) * (1.0 - LOSS_A * LOSS_A));
    float phi0 = (float)fmod(2.0 * PI * N_EFF * (2.0 * PI * RADIUS) / LAMBDA,
                             2.0 * PI);

    prep_all<<<1088, 256>>>(x, off, out, K, phi0);
    photonic_main<<<2048, 128>>>(out, C2, D);
}